// round 9
// baseline (speedup 1.0000x reference)
#include <cuda_runtime.h>
#include <cuda_fp16.h>
#include <math.h>

#define C_ 128
#define H_ 32
#define K_ 15
#define KG_ 120
#define QB 4
#define W1P 132   // pitch W1^T [32][132]
#define W2P 36    // pitch W2^T [128][36]
#define WARPS 10
#define THREADS 320
#define NBLK 296
#define NMAX 30720

// per-warp region (floats), lifetime-aliased:
//   [0..1024)    ws[4][32][8]   (phases D,E)   — overlays csm[0..512) + hsm[512..640) (phases A..C)
//   [1024..1536) cwsm[4][128]   (phases C,D)
#define OFF_CSM  0
#define OFF_HSM  512
#define OFF_WS   0
#define OFF_CWSM 1024
#define WARP_SMEM 1536
// block-wide: W1t(4224) + W2t(4608) + b1(32) + b2(128) + kpt(64) + psum(128) + psq(128)
#define BLOCK_FIXED (32*W1P + 128*W2P + 32 + 128 + 64 + 128 + 128)   // 9312
#define SMEM_FLOATS (BLOCK_FIXED + WARPS*WARP_SMEM)                   // 24672 fl = 98.7KB

typedef unsigned long long ull;
#define FMA2(d,a,b,c) asm("fma.rn.f32x2 %0, %1, %2, %3;" : "=l"(d) : "l"(a), "l"(b), "l"(c))
#define ADD2(d,a,b)   asm("add.rn.f32x2 %0, %1, %2;" : "=l"(d) : "l"(a), "l"(b))
#define PACK2(d,x)    asm("mov.b64 %0, {%1, %1};" : "=l"(d) : "f"(x))
#define UNPK2(lo,hi,p) asm("mov.b64 {%0, %1}, %2;" : "=f"(lo), "=f"(hi) : "l"(p))
#define SQRTA(d,x)    asm("sqrt.approx.f32 %0, %1;" : "=f"(d) : "f"(x))

__device__ float g_sum[C_];
__device__ float g_sq[C_];
__device__ __align__(16) __half g_sf16[NMAX * C_];

// convert s_feats fp32 -> fp16 cache; block 0 also zeroes the BN accumulators
__global__ void kp_cvt_kernel(const float* __restrict__ sf, int total4) {
    int i = blockIdx.x * blockDim.x + threadIdx.x;
    if (blockIdx.x == 0 && threadIdx.x < C_) {
        g_sum[threadIdx.x] = 0.f;
        g_sq[threadIdx.x]  = 0.f;
    }
    if (i < total4) {
        float4 v = ((const float4*)sf)[i];
        __half2 h0 = __floats2half2_rn(v.x, v.y);
        __half2 h1 = __floats2half2_rn(v.z, v.w);
        uint2 p;
        p.x = *(unsigned int*)&h0;
        p.y = *(unsigned int*)&h1;
        ((uint2*)g_sf16)[i] = p;
    }
}

__global__ __launch_bounds__(THREADS, 2) void kp_main_kernel(
    const float* __restrict__ qp,   // (M,3)
    const float* __restrict__ sp,   // (N,3)
    const float* __restrict__ sf,   // (N,128) fp32
    const int*   __restrict__ nidx, // (M,32)
    const float* __restrict__ kp,   // (15,3)
    const float* __restrict__ W1,   // (128,32)
    const float* __restrict__ b1,   // (32)
    const float* __restrict__ W2,   // (32,120)
    const float* __restrict__ b2,   // (120)
    float* __restrict__ out,        // (M,128) pre-BN
    int M)
{
    extern __shared__ float smem[];
    float* W1t  = smem;                 // [32][132]
    float* W2t  = W1t + 32 * W1P;       // [128][36]
    float* b1s  = W2t + 128 * W2P;      // [32]
    float* b2s  = b1s + 32;             // [128]
    float* kpt  = b2s + 128;            // [16][4]: (-2kx,-2ky,-2kz,|k|^2)
    float* psum = kpt + 64;             // [128]
    float* psq  = psum + 128;           // [128]
    float* wreg = psq + 128;

    const int tid  = threadIdx.x;
    const int wid  = tid >> 5;
    const int lane = tid & 31;

    float* wbase = wreg + wid * WARP_SMEM;
    float* csm   = wbase + OFF_CSM;     // [4][128]  (phases A,B)
    float* hsm   = wbase + OFF_HSM;     // [4][32]   (phases B,C)
    float* cwsm  = wbase + OFF_CWSM;    // [4][128]  (phases C,D)
    float* ws    = wbase + OFF_WS;      // [4][32][8] (phases D,E; aliases csm/hsm)

    for (int e = tid; e < 128 * 32; e += THREADS) {
        int c = e >> 5, i = e & 31;
        W1t[i * W1P + c] = W1[e];
    }
    for (int e = tid; e < 128 * 32; e += THREADS) {
        int i = e >> 7, kg = e & 127;
        W2t[kg * W2P + i] = (kg < KG_) ? W2[i * KG_ + kg] : 0.f;
    }
    if (tid < 32)  b1s[tid] = b1[tid];
    if (tid < 128) { b2s[tid] = (tid < KG_) ? b2[tid] : 0.f; psum[tid] = 0.f; psq[tid] = 0.f; }
    if (tid < K_) {
        float kx = kp[tid * 3 + 0], ky = kp[tid * 3 + 1], kz = kp[tid * 3 + 2];
        float4 t = make_float4(-2.f * kx, -2.f * ky, -2.f * kz,
                               fmaf(kx, kx, fmaf(ky, ky, kz * kz)));
        ((float4*)kpt)[tid] = t;
    }
    __syncthreads();

    ull lsum01 = 0, lsum23 = 0, lsq01 = 0, lsq23 = 0;

    const int gw = blockIdx.x * WARPS + wid;
    const int nw = gridDim.x * WARPS;
    const int g  = lane >> 2;

    for (int mb = gw * QB; mb < M; mb += nw * QB) {
        // ---- A: neighbor indices (regs) + center feats for up to 4 queries ----
        int idxq[QB];
        #pragma unroll
        for (int q = 0; q < QB; q++) {
            int mq = mb + q;
            idxq[q] = (mq < M) ? nidx[mq * H_ + lane] : 0;
        }
        #pragma unroll
        for (int q = 0; q < QB; q++) {
            int i0 = __shfl_sync(0xffffffffu, idxq[q], 0);
            float4 cf = __ldg(&((const float4*)sf)[i0 * 32 + lane]);
            ((float4*)&csm[q * 128])[lane] = cf;
        }
        __syncwarp();

        // ---- B: batched MLP1 ----
        {
            ull hvp[QB];
            #pragma unroll
            for (int q = 0; q < QB; q++) hvp[q] = 0;
            #pragma unroll 8
            for (int cc = 0; cc < 32; cc++) {
                ulonglong2 w = *(ulonglong2*)&W1t[lane * W1P + cc * 4];
                #pragma unroll
                for (int q = 0; q < QB; q++) {
                    ulonglong2 c = *(ulonglong2*)&csm[q * 128 + cc * 4];
                    FMA2(hvp[q], c.x, w.x, hvp[q]);
                    FMA2(hvp[q], c.y, w.y, hvp[q]);
                }
            }
            float bb = b1s[lane];
            #pragma unroll
            for (int q = 0; q < QB; q++) {
                float lo, hi; UNPK2(lo, hi, hvp[q]);
                float hv = bb + lo + hi;
                hv = (hv > 0.f) ? hv : 0.1f * hv;
                hsm[q * 32 + lane] = hv;
            }
        }
        __syncwarp();

        // ---- C: batched MLP2 ----
        {
            ull accp[4][QB];
            #pragma unroll
            for (int r = 0; r < 4; r++)
                #pragma unroll
                for (int q = 0; q < QB; q++) accp[r][q] = 0;
            #pragma unroll
            for (int ii = 0; ii < 8; ii++) {
                ulonglong2 h2[QB];
                #pragma unroll
                for (int q = 0; q < QB; q++)
                    h2[q] = *(ulonglong2*)&hsm[q * 32 + ii * 4];
                #pragma unroll
                for (int r = 0; r < 4; r++) {
                    ulonglong2 w = *(ulonglong2*)&W2t[(lane + 32 * r) * W2P + ii * 4];
                    #pragma unroll
                    for (int q = 0; q < QB; q++) {
                        FMA2(accp[r][q], h2[q].x, w.x, accp[r][q]);
                        FMA2(accp[r][q], h2[q].y, w.y, accp[r][q]);
                    }
                }
            }
            #pragma unroll
            for (int r = 0; r < 4; r++) {
                int kg = lane + 32 * r;
                float bb = b2s[kg];
                #pragma unroll
                for (int q = 0; q < QB; q++) {
                    float lo, hi; UNPK2(lo, hi, accp[r][q]);
                    cwsm[q * 128 + kg] = bb + lo + hi;
                }
            }
        }
        __syncwarp();

        // ---- D: influence + combine for ALL 4 queries (lane = h) ----
        // NOTE: ws aliases csm/hsm — both dead by now (last read in phase C).
        #pragma unroll 1
        for (int q = 0; q < QB; q++) {
            int mq = mb + q;
            int mc = (mq < M) ? mq : (M - 1);   // clamp; pad results discarded

            float qx = qp[mc * 3 + 0], qy = qp[mc * 3 + 1], qz = qp[mc * 3 + 2];
            int myidx = idxq[q];
            float dx = sp[myidx * 3 + 0] - qx;
            float dy = sp[myidx * 3 + 1] - qy;
            float dz = sp[myidx * 3 + 2] - qz;
            float dd = fmaf(dx, dx, fmaf(dy, dy, dz * dz));
            float infl[K_];
            #pragma unroll
            for (int k = 0; k < K_; k++) {
                float4 t = ((float4*)kpt)[k];
                float sq = fmaf(dx, t.x, fmaf(dy, t.y, fmaf(dz, t.z, dd + t.w)));
                sq = fmaxf(sq, 0.f);
                float d; SQRTA(d, sq);
                infl[k] = fmaxf(1.f - 0.5f * d, 0.f);
            }

            ull w01 = 0, w23 = 0, w45 = 0, w67 = 0;
            const float* cwq = &cwsm[q * 128];
            #pragma unroll
            for (int k = 0; k < K_; k++) {
                ulonglong2 p0 = *(ulonglong2*)&cwq[k * 8];
                ulonglong2 p1 = *(ulonglong2*)&cwq[k * 8 + 4];
                ull ik2; PACK2(ik2, infl[k]);
                FMA2(w01, ik2, p0.x, w01);
                FMA2(w23, ik2, p0.y, w23);
                FMA2(w45, ik2, p1.x, w45);
                FMA2(w67, ik2, p1.y, w67);
            }
            ulonglong2* wrow = (ulonglong2*)&ws[q * 256 + lane * 8];
            wrow[0] = make_ulonglong2(w01, w23);
            wrow[1] = make_ulonglong2(w45, w67);
        }
        __syncwarp();

        // ---- E: interleaved gather-accumulate for 4 queries ----
        {
            ull a01[QB], a23[QB];
            #pragma unroll
            for (int q = 0; q < QB; q++) { a01[q] = 0; a23[q] = 0; }

            #pragma unroll 8
            for (int h = 0; h < H_; h++) {
                #pragma unroll
                for (int q = 0; q < QB; q++) {
                    float wv = ws[q * 256 + h * 8 + g];
                    ull wv2; PACK2(wv2, wv);
                    int ih = __shfl_sync(0xffffffffu, idxq[q], h);
                    uint2 f = *(const uint2*)(g_sf16 + ih * C_ + lane * 4);
                    float2 lo = __half22float2(*(__half2*)&f.x);
                    float2 hi = __half22float2(*(__half2*)&f.y);
                    ull plo = *(ull*)&lo;
                    ull phi = *(ull*)&hi;
                    FMA2(a01[q], plo, wv2, a01[q]);
                    FMA2(a23[q], phi, wv2, a23[q]);
                }
            }

            #pragma unroll
            for (int q = 0; q < QB; q++) {
                int mq = mb + q;
                if (mq < M) {
                    float x0, x1, x2, x3;
                    UNPK2(x0, x1, a01[q]);
                    UNPK2(x2, x3, a23[q]);
                    ((float4*)out)[mq * 32 + lane] = make_float4(x0, x1, x2, x3);
                    ADD2(lsum01, lsum01, a01[q]);
                    ADD2(lsum23, lsum23, a23[q]);
                    FMA2(lsq01, a01[q], a01[q], lsq01);
                    FMA2(lsq23, a23[q], a23[q], lsq23);
                }
            }
        }
        __syncwarp();  // ws dead; csm reused next batch
    }

    // ---- BN statistics reduction ----
    __syncthreads();
    float s0, s1, s2, s3, q0, q1, q2, q3;
    UNPK2(s0, s1, lsum01); UNPK2(s2, s3, lsum23);
    UNPK2(q0, q1, lsq01);  UNPK2(q2, q3, lsq23);
    int cb = lane * 4;
    atomicAdd(&psum[cb + 0], s0); atomicAdd(&psq[cb + 0], q0);
    atomicAdd(&psum[cb + 1], s1); atomicAdd(&psq[cb + 1], q1);
    atomicAdd(&psum[cb + 2], s2); atomicAdd(&psq[cb + 2], q2);
    atomicAdd(&psum[cb + 3], s3); atomicAdd(&psq[cb + 3], q3);
    __syncthreads();
    if (tid < 128) {
        atomicAdd(&g_sum[tid], psum[tid]);
        atomicAdd(&g_sq[tid],  psq[tid]);
    }
}

// fused stats + normalize + leaky
__global__ __launch_bounds__(256) void kp_norm_kernel(
    float* __restrict__ out,
    const float* __restrict__ gamma,
    const float* __restrict__ beta,
    float invM, int total4)
{
    __shared__ float ssc[128], ssh[128];
    int t = threadIdx.x;
    if (t < 128) {
        float mean = g_sum[t] * invM;
        float var  = fmaxf(g_sq[t] * invM - mean * mean, 0.f);
        float sc   = gamma[t] * rsqrtf(var + 1e-5f);
        ssc[t] = sc;
        ssh[t] = beta[t] - mean * sc;
    }
    __syncthreads();

    int i = blockIdx.x * blockDim.x + t;
    if (i < total4) {
        float4 v = ((float4*)out)[i];
        int cb = (i & 31) * 4;
        v.x = fmaf(v.x, ssc[cb + 0], ssh[cb + 0]);
        v.y = fmaf(v.y, ssc[cb + 1], ssh[cb + 1]);
        v.z = fmaf(v.z, ssc[cb + 2], ssh[cb + 2]);
        v.w = fmaf(v.w, ssc[cb + 3], ssh[cb + 3]);
        v.x = (v.x > 0.f) ? v.x : 0.1f * v.x;
        v.y = (v.y > 0.f) ? v.y : 0.1f * v.y;
        v.z = (v.z > 0.f) ? v.z : 0.1f * v.z;
        v.w = (v.w > 0.f) ? v.w : 0.1f * v.w;
        ((float4*)out)[i] = v;
    }
}

extern "C" void kernel_launch(void* const* d_in, const int* in_sizes, int n_in,
                              void* d_out, int out_size) {
    const float* qp    = (const float*)d_in[0];
    const float* sp    = (const float*)d_in[1];
    const float* sf    = (const float*)d_in[2];
    const int*   nidx  = (const int*)d_in[3];
    const float* kp    = (const float*)d_in[4];
    const float* W1    = (const float*)d_in[5];
    const float* b1    = (const float*)d_in[6];
    const float* W2    = (const float*)d_in[7];
    const float* b2    = (const float*)d_in[8];
    const float* gamma = (const float*)d_in[9];
    const float* beta  = (const float*)d_in[10];
    float* out = (float*)d_out;

    int M = in_sizes[0] / 3;
    int N = in_sizes[2] / C_;
    if (N > NMAX) N = NMAX;

    size_t smem_bytes = (size_t)SMEM_FLOATS * sizeof(float);
    cudaFuncSetAttribute(kp_main_kernel,
                         cudaFuncAttributeMaxDynamicSharedMemorySize, (int)smem_bytes);

    int cvt4 = N * 32;
    kp_cvt_kernel<<<(cvt4 + 255) / 256, 256>>>(sf, cvt4);
    kp_main_kernel<<<NBLK, THREADS, smem_bytes>>>(qp, sp, sf, nidx, kp, W1, b1, W2, b2, out, M);
    int total4 = M * 32;
    kp_norm_kernel<<<(total4 + 255) / 256, 256>>>(out, gamma, beta, 1.0f / (float)M, total4);
}

// round 10
// speedup vs baseline: 1.1415x; 1.1415x over previous
#include <cuda_runtime.h>
#include <cuda_fp16.h>
#include <math.h>

#define C_ 128
#define H_ 32
#define K_ 15
#define KG_ 120
#define QB 4
#define W1P 132   // pitch W1^T [32][132]
#define W2P 36    // pitch W2^T [128][36]
#define WARPS 8
#define THREADS 256
#define NBLK 296
#define NMAX 30720

// per-warp region (floats): csm 512 | hsm 128 | cwsm 512 | ws 4*256 | idxs 128 | pad
#define OFF_CSM  0
#define OFF_HSM  512
#define OFF_CWSM 640
#define OFF_WS   1152
#define OFF_IDX  2176
#define WARP_SMEM 2312
// block-wide: W1t(4224) + W2t(4608) + b1(32) + b2(128) + kpt(64) + psum(128) + psq(128)
#define BLOCK_FIXED (32*W1P + 128*W2P + 32 + 128 + 64 + 128 + 128)   // 9312
#define SMEM_FLOATS (BLOCK_FIXED + WARPS*WARP_SMEM)

typedef unsigned long long ull;
#define FMA2(d,a,b,c) asm("fma.rn.f32x2 %0, %1, %2, %3;" : "=l"(d) : "l"(a), "l"(b), "l"(c))
#define ADD2(d,a,b)   asm("add.rn.f32x2 %0, %1, %2;" : "=l"(d) : "l"(a), "l"(b))
#define PACK2(d,x)    asm("mov.b64 %0, {%1, %1};" : "=l"(d) : "f"(x))
#define UNPK2(lo,hi,p) asm("mov.b64 {%0, %1}, %2;" : "=f"(lo), "=f"(hi) : "l"(p))
#define SQRTA(d,x)    asm("sqrt.approx.f32 %0, %1;" : "=f"(d) : "f"(x))

__device__ float g_sum[C_];
__device__ float g_sq[C_];
__device__ __align__(16) __half g_sf16[NMAX * C_];

// convert s_feats fp32 -> fp16 cache; block 0 also zeroes the BN accumulators
__global__ void kp_cvt_kernel(const float* __restrict__ sf, int total4) {
    int i = blockIdx.x * blockDim.x + threadIdx.x;
    if (blockIdx.x == 0 && threadIdx.x < C_) {
        g_sum[threadIdx.x] = 0.f;
        g_sq[threadIdx.x]  = 0.f;
    }
    if (i < total4) {
        float4 v = ((const float4*)sf)[i];
        __half2 h0 = __floats2half2_rn(v.x, v.y);
        __half2 h1 = __floats2half2_rn(v.z, v.w);
        uint2 p;
        p.x = *(unsigned int*)&h0;
        p.y = *(unsigned int*)&h1;
        ((uint2*)g_sf16)[i] = p;
    }
}

__global__ __launch_bounds__(THREADS, 2) void kp_main_kernel(
    const float* __restrict__ qp,   // (M,3)
    const float* __restrict__ sp,   // (N,3)
    const float* __restrict__ sf,   // (N,128) fp32
    const int*   __restrict__ nidx, // (M,32)
    const float* __restrict__ kp,   // (15,3)
    const float* __restrict__ W1,   // (128,32)
    const float* __restrict__ b1,   // (32)
    const float* __restrict__ W2,   // (32,120)
    const float* __restrict__ b2,   // (120)
    float* __restrict__ out,        // (M,128) pre-BN
    int M)
{
    extern __shared__ float smem[];
    float* W1t  = smem;                 // [32][132]
    float* W2t  = W1t + 32 * W1P;       // [128][36]
    float* b1s  = W2t + 128 * W2P;      // [32]
    float* b2s  = b1s + 32;             // [128]
    float* kpt  = b2s + 128;            // [16][4]: (-2kx,-2ky,-2kz,|k|^2)
    float* psum = kpt + 64;             // [128]
    float* psq  = psum + 128;           // [128]
    float* wreg = psq + 128;

    const int tid  = threadIdx.x;
    const int wid  = tid >> 5;
    const int lane = tid & 31;

    float* wbase = wreg + wid * WARP_SMEM;
    float* csm   = wbase + OFF_CSM;     // [4][128]
    float* hsm   = wbase + OFF_HSM;     // [4][32]
    float* cwsm  = wbase + OFF_CWSM;    // [4][128]
    float* ws    = wbase + OFF_WS;      // [4][32][8]  ws[q][h][g]
    int*   idxs  = (int*)(wbase + OFF_IDX); // [4][32]

    for (int e = tid; e < 128 * 32; e += THREADS) {
        int c = e >> 5, i = e & 31;
        W1t[i * W1P + c] = W1[e];
    }
    for (int e = tid; e < 128 * 32; e += THREADS) {
        int i = e >> 7, kg = e & 127;
        W2t[kg * W2P + i] = (kg < KG_) ? W2[i * KG_ + kg] : 0.f;
    }
    if (tid < 32)  b1s[tid] = b1[tid];
    if (tid < 128) { b2s[tid] = (tid < KG_) ? b2[tid] : 0.f; psum[tid] = 0.f; psq[tid] = 0.f; }
    if (tid < K_) {
        float kx = kp[tid * 3 + 0], ky = kp[tid * 3 + 1], kz = kp[tid * 3 + 2];
        float4 t4 = make_float4(-2.f * kx, -2.f * ky, -2.f * kz,
                                fmaf(kx, kx, fmaf(ky, ky, kz * kz)));
        ((float4*)kpt)[tid] = t4;
    }
    __syncthreads();

    ull lsum01 = 0, lsum23 = 0, lsq01 = 0, lsq23 = 0;

    const int gw = blockIdx.x * WARPS + wid;
    const int nw = gridDim.x * WARPS;
    const int g  = lane >> 2;

    // strided assignment: warp handles queries gw, gw+nw, gw+2nw, ...
    // batch b covers m(q) = t + q*nw with t = gw + b*QB*nw.
    int t = gw;

    // ---------------- full batches (all 4 queries valid) ----------------
    while (t + 3 * nw < M) {
        // ---- A: neighbor indices + center feats ----
        int idxq[QB];
        #pragma unroll
        for (int q = 0; q < QB; q++) {
            idxq[q] = nidx[(t + q * nw) * H_ + lane];
            idxs[q * 32 + lane] = idxq[q];
        }
        #pragma unroll
        for (int q = 0; q < QB; q++) {
            int i0 = __shfl_sync(0xffffffffu, idxq[q], 0);
            float4 cf = __ldg(&((const float4*)sf)[i0 * 32 + lane]);
            ((float4*)&csm[q * 128])[lane] = cf;
        }
        __syncwarp();

        // ---- B: batched MLP1 ----
        {
            ull hvp[QB];
            #pragma unroll
            for (int q = 0; q < QB; q++) hvp[q] = 0;
            #pragma unroll 8
            for (int cc = 0; cc < 32; cc++) {
                ulonglong2 w = *(ulonglong2*)&W1t[lane * W1P + cc * 4];
                #pragma unroll
                for (int q = 0; q < QB; q++) {
                    ulonglong2 c = *(ulonglong2*)&csm[q * 128 + cc * 4];
                    FMA2(hvp[q], c.x, w.x, hvp[q]);
                    FMA2(hvp[q], c.y, w.y, hvp[q]);
                }
            }
            float bb = b1s[lane];
            #pragma unroll
            for (int q = 0; q < QB; q++) {
                float lo, hi; UNPK2(lo, hi, hvp[q]);
                float hv = bb + lo + hi;
                hv = (hv > 0.f) ? hv : 0.1f * hv;
                hsm[q * 32 + lane] = hv;
            }
        }
        __syncwarp();

        // ---- C: batched MLP2 ----
        {
            ull accp[4][QB];
            #pragma unroll
            for (int r = 0; r < 4; r++)
                #pragma unroll
                for (int q = 0; q < QB; q++) accp[r][q] = 0;
            #pragma unroll
            for (int ii = 0; ii < 8; ii++) {
                ulonglong2 h2[QB];
                #pragma unroll
                for (int q = 0; q < QB; q++)
                    h2[q] = *(ulonglong2*)&hsm[q * 32 + ii * 4];
                #pragma unroll
                for (int r = 0; r < 4; r++) {
                    ulonglong2 w = *(ulonglong2*)&W2t[(lane + 32 * r) * W2P + ii * 4];
                    #pragma unroll
                    for (int q = 0; q < QB; q++) {
                        FMA2(accp[r][q], h2[q].x, w.x, accp[r][q]);
                        FMA2(accp[r][q], h2[q].y, w.y, accp[r][q]);
                    }
                }
            }
            #pragma unroll
            for (int r = 0; r < 4; r++) {
                int kg = lane + 32 * r;
                float bb = b2s[kg];
                #pragma unroll
                for (int q = 0; q < QB; q++) {
                    float lo, hi; UNPK2(lo, hi, accp[r][q]);
                    cwsm[q * 128 + kg] = bb + lo + hi;
                }
            }
        }
        __syncwarp();

        // ---- D: influence + combine (lane = h) ----
        #pragma unroll 1
        for (int q = 0; q < QB; q++) {
            int mq = t + q * nw;
            float qx = qp[mq * 3 + 0], qy = qp[mq * 3 + 1], qz = qp[mq * 3 + 2];
            int myidx = idxq[q];
            float dx = sp[myidx * 3 + 0] - qx;
            float dy = sp[myidx * 3 + 1] - qy;
            float dz = sp[myidx * 3 + 2] - qz;
            float dd = fmaf(dx, dx, fmaf(dy, dy, dz * dz));
            float infl[K_];
            #pragma unroll
            for (int k = 0; k < K_; k++) {
                float4 t4 = ((float4*)kpt)[k];
                float sq = fmaf(dx, t4.x, fmaf(dy, t4.y, fmaf(dz, t4.z, dd + t4.w)));
                sq = fmaxf(sq, 0.f);
                float d; SQRTA(d, sq);
                infl[k] = fmaxf(1.f - 0.5f * d, 0.f);
            }

            ull w01 = 0, w23 = 0, w45 = 0, w67 = 0;
            const float* cwq = &cwsm[q * 128];
            #pragma unroll
            for (int k = 0; k < K_; k++) {
                ulonglong2 p0 = *(ulonglong2*)&cwq[k * 8];
                ulonglong2 p1 = *(ulonglong2*)&cwq[k * 8 + 4];
                ull ik2; PACK2(ik2, infl[k]);
                FMA2(w01, ik2, p0.x, w01);
                FMA2(w23, ik2, p0.y, w23);
                FMA2(w45, ik2, p1.x, w45);
                FMA2(w67, ik2, p1.y, w67);
            }
            ulonglong2* wrow = (ulonglong2*)&ws[q * 256 + lane * 8];
            wrow[0] = make_ulonglong2(w01, w23);
            wrow[1] = make_ulonglong2(w45, w67);
        }
        __syncwarp();

        // ---- E: interleaved gather-accumulate ----
        {
            ull a01[QB], a23[QB];
            #pragma unroll
            for (int q = 0; q < QB; q++) { a01[q] = 0; a23[q] = 0; }

            #pragma unroll 8
            for (int h = 0; h < H_; h++) {
                #pragma unroll
                for (int q = 0; q < QB; q++) {
                    float wv = ws[q * 256 + h * 8 + g];
                    ull wv2; PACK2(wv2, wv);
                    int ih = idxs[q * 32 + h];
                    uint2 f = *(const uint2*)(g_sf16 + ih * C_ + lane * 4);
                    float2 lo = __half22float2(*(__half2*)&f.x);
                    float2 hi = __half22float2(*(__half2*)&f.y);
                    ull plo = *(ull*)&lo;
                    ull phi = *(ull*)&hi;
                    FMA2(a01[q], plo, wv2, a01[q]);
                    FMA2(a23[q], phi, wv2, a23[q]);
                }
            }

            #pragma unroll
            for (int q = 0; q < QB; q++) {
                int mq = t + q * nw;
                float x0, x1, x2, x3;
                UNPK2(x0, x1, a01[q]);
                UNPK2(x2, x3, a23[q]);
                ((float4*)out)[mq * 32 + lane] = make_float4(x0, x1, x2, x3);
                ADD2(lsum01, lsum01, a01[q]);
                ADD2(lsum23, lsum23, a23[q]);
                FMA2(lsq01, a01[q], a01[q], lsq01);
                FMA2(lsq23, a23[q], a23[q], lsq23);
            }
        }
        __syncwarp();
        t += QB * nw;
    }

    // ---------------- tail: remaining single queries (<= 3, usually 1) ----------------
    for (; t < M; t += nw) {
        int m = t;
        int myidx = nidx[m * H_ + lane];
        idxs[lane] = myidx;
        {
            int i0 = __shfl_sync(0xffffffffu, myidx, 0);
            float4 cf = __ldg(&((const float4*)sf)[i0 * 32 + lane]);
            ((float4*)csm)[lane] = cf;
        }
        __syncwarp();

        // MLP1
        {
            ull hvp = 0;
            #pragma unroll 8
            for (int cc = 0; cc < 32; cc++) {
                ulonglong2 w = *(ulonglong2*)&W1t[lane * W1P + cc * 4];
                ulonglong2 c = *(ulonglong2*)&csm[cc * 4];
                FMA2(hvp, c.x, w.x, hvp);
                FMA2(hvp, c.y, w.y, hvp);
            }
            float lo, hi; UNPK2(lo, hi, hvp);
            float hv = b1s[lane] + lo + hi;
            hv = (hv > 0.f) ? hv : 0.1f * hv;
            hsm[lane] = hv;
        }
        __syncwarp();

        // MLP2
        {
            ull acc[4];
            #pragma unroll
            for (int r = 0; r < 4; r++) acc[r] = 0;
            #pragma unroll
            for (int ii = 0; ii < 8; ii++) {
                ulonglong2 h2 = *(ulonglong2*)&hsm[ii * 4];
                #pragma unroll
                for (int r = 0; r < 4; r++) {
                    ulonglong2 w = *(ulonglong2*)&W2t[(lane + 32 * r) * W2P + ii * 4];
                    FMA2(acc[r], h2.x, w.x, acc[r]);
                    FMA2(acc[r], h2.y, w.y, acc[r]);
                }
            }
            #pragma unroll
            for (int r = 0; r < 4; r++) {
                int kg = lane + 32 * r;
                float lo, hi; UNPK2(lo, hi, acc[r]);
                cwsm[kg] = b2s[kg] + lo + hi;
            }
        }
        __syncwarp();

        // influence + combine (lane = h)
        {
            float qx = qp[m * 3 + 0], qy = qp[m * 3 + 1], qz = qp[m * 3 + 2];
            float dx = sp[myidx * 3 + 0] - qx;
            float dy = sp[myidx * 3 + 1] - qy;
            float dz = sp[myidx * 3 + 2] - qz;
            float dd = fmaf(dx, dx, fmaf(dy, dy, dz * dz));
            ull w01 = 0, w23 = 0, w45 = 0, w67 = 0;
            #pragma unroll
            for (int k = 0; k < K_; k++) {
                float4 t4 = ((float4*)kpt)[k];
                float sq = fmaf(dx, t4.x, fmaf(dy, t4.y, fmaf(dz, t4.z, dd + t4.w)));
                sq = fmaxf(sq, 0.f);
                float d; SQRTA(d, sq);
                float ik = fmaxf(1.f - 0.5f * d, 0.f);
                ulonglong2 p0 = *(ulonglong2*)&cwsm[k * 8];
                ulonglong2 p1 = *(ulonglong2*)&cwsm[k * 8 + 4];
                ull ik2; PACK2(ik2, ik);
                FMA2(w01, ik2, p0.x, w01);
                FMA2(w23, ik2, p0.y, w23);
                FMA2(w45, ik2, p1.x, w45);
                FMA2(w67, ik2, p1.y, w67);
            }
            ulonglong2* wrow = (ulonglong2*)&ws[lane * 8];
            wrow[0] = make_ulonglong2(w01, w23);
            wrow[1] = make_ulonglong2(w45, w67);
        }
        __syncwarp();

        // gather
        {
            ull a01 = 0, a23 = 0;
            #pragma unroll 8
            for (int h = 0; h < H_; h++) {
                float wv = ws[h * 8 + g];
                ull wv2; PACK2(wv2, wv);
                int ih = idxs[h];
                uint2 f = *(const uint2*)(g_sf16 + ih * C_ + lane * 4);
                float2 lo = __half22float2(*(__half2*)&f.x);
                float2 hi = __half22float2(*(__half2*)&f.y);
                ull plo = *(ull*)&lo;
                ull phi = *(ull*)&hi;
                FMA2(a01, plo, wv2, a01);
                FMA2(a23, phi, wv2, a23);
            }
            float x0, x1, x2, x3;
            UNPK2(x0, x1, a01);
            UNPK2(x2, x3, a23);
            ((float4*)out)[m * 32 + lane] = make_float4(x0, x1, x2, x3);
            ADD2(lsum01, lsum01, a01);
            ADD2(lsum23, lsum23, a23);
            FMA2(lsq01, a01, a01, lsq01);
            FMA2(lsq23, a23, a23, lsq23);
        }
        __syncwarp();
    }

    // ---- BN statistics reduction ----
    __syncthreads();
    float s0, s1, s2, s3, q0, q1, q2, q3;
    UNPK2(s0, s1, lsum01); UNPK2(s2, s3, lsum23);
    UNPK2(q0, q1, lsq01);  UNPK2(q2, q3, lsq23);
    int cb = lane * 4;
    atomicAdd(&psum[cb + 0], s0); atomicAdd(&psq[cb + 0], q0);
    atomicAdd(&psum[cb + 1], s1); atomicAdd(&psq[cb + 1], q1);
    atomicAdd(&psum[cb + 2], s2); atomicAdd(&psq[cb + 2], q2);
    atomicAdd(&psum[cb + 3], s3); atomicAdd(&psq[cb + 3], q3);
    __syncthreads();
    if (tid < 128) {
        atomicAdd(&g_sum[tid], psum[tid]);
        atomicAdd(&g_sq[tid],  psq[tid]);
    }
}

// fused stats + normalize + leaky
__global__ __launch_bounds__(256) void kp_norm_kernel(
    float* __restrict__ out,
    const float* __restrict__ gamma,
    const float* __restrict__ beta,
    float invM, int total4)
{
    __shared__ float ssc[128], ssh[128];
    int t = threadIdx.x;
    if (t < 128) {
        float mean = g_sum[t] * invM;
        float var  = fmaxf(g_sq[t] * invM - mean * mean, 0.f);
        float sc   = gamma[t] * rsqrtf(var + 1e-5f);
        ssc[t] = sc;
        ssh[t] = beta[t] - mean * sc;
    }
    __syncthreads();

    int i = blockIdx.x * blockDim.x + t;
    if (i < total4) {
        float4 v = ((float4*)out)[i];
        int cb = (i & 31) * 4;
        v.x = fmaf(v.x, ssc[cb + 0], ssh[cb + 0]);
        v.y = fmaf(v.y, ssc[cb + 1], ssh[cb + 1]);
        v.z = fmaf(v.z, ssc[cb + 2], ssh[cb + 2]);
        v.w = fmaf(v.w, ssc[cb + 3], ssh[cb + 3]);
        v.x = (v.x > 0.f) ? v.x : 0.1f * v.x;
        v.y = (v.y > 0.f) ? v.y : 0.1f * v.y;
        v.z = (v.z > 0.f) ? v.z : 0.1f * v.z;
        v.w = (v.w > 0.f) ? v.w : 0.1f * v.w;
        ((float4*)out)[i] = v;
    }
}

extern "C" void kernel_launch(void* const* d_in, const int* in_sizes, int n_in,
                              void* d_out, int out_size) {
    const float* qp    = (const float*)d_in[0];
    const float* sp    = (const float*)d_in[1];
    const float* sf    = (const float*)d_in[2];
    const int*   nidx  = (const int*)d_in[3];
    const float* kp    = (const float*)d_in[4];
    const float* W1    = (const float*)d_in[5];
    const float* b1    = (const float*)d_in[6];
    const float* W2    = (const float*)d_in[7];
    const float* b2    = (const float*)d_in[8];
    const float* gamma = (const float*)d_in[9];
    const float* beta  = (const float*)d_in[10];
    float* out = (float*)d_out;

    int M = in_sizes[0] / 3;
    int N = in_sizes[2] / C_;
    if (N > NMAX) N = NMAX;

    size_t smem_bytes = (size_t)SMEM_FLOATS * sizeof(float);
    cudaFuncSetAttribute(kp_main_kernel,
                         cudaFuncAttributeMaxDynamicSharedMemorySize, (int)smem_bytes);

    int cvt4 = N * 32;
    kp_cvt_kernel<<<(cvt4 + 255) / 256, 256>>>(sf, cvt4);
    kp_main_kernel<<<NBLK, THREADS, smem_bytes>>>(qp, sp, sf, nidx, kp, W1, b1, W2, b2, out, M);
    int total4 = M * 32;
    kp_norm_kernel<<<(total4 + 255) / 256, 256>>>(out, gamma, beta, 1.0f / (float)M, total4);
}